// round 9
// baseline (speedup 1.0000x reference)
#include <cuda_runtime.h>
#include <math.h>

#define NB    2048
#define HID   64
#define TAU   22

__device__ float g_C[2][2][7];          // [graph][{C1,C2}][f]
__device__ float g_M[2][TAU][HID];      // [graph][t][k] = sum_m W2_g[k][m]*fc2W[m][t]

__device__ __forceinline__ float eluf(float x) { return x > 0.0f ? x : (__expf(x) - 1.0f); }

// ---------- setup: batch-invariant precompute (~1us) ----------
__global__ void __launch_bounds__(128) k_setup(
    const float* __restrict__ uW1, const float* __restrict__ uA,
    const float* __restrict__ uW2,
    const float* __restrict__ dW1, const float* __restrict__ dA,
    const float* __restrict__ dW2,
    const float* __restrict__ fc2W)
{
    const int id = blockIdx.x * 128 + threadIdx.x;   // 23*128 = 2944 >= 2844
    if (id < 28) {
        int g = id / 14, rem = id % 14, which = rem / 7, f = rem % 7;
        const float* W1 = g ? dW1 : uW1;
        const float* A  = (g ? dA : uA) + which * HID;
        float acc = 0.0f;
        #pragma unroll 8
        for (int k = 0; k < HID; k++) acc = fmaf(W1[f * HID + k], A[k], acc);
        g_C[g][which][f] = acc;
    } else if (id - 28 < 2 * TAU * HID) {
        int e = id - 28;
        int g = e / (TAU * HID); e -= g * TAU * HID;
        int t = e / HID, k = e - t * HID;
        const float* W2 = g ? dW2 : uW2;
        float acc = 0.0f;
        #pragma unroll 8
        for (int m = 0; m < HID; m++)
            acc = fmaf(W2[k * HID + m], fc2W[m * TAU + t], acc);
        g_M[g][t][k] = acc;
    }
}

// ---------- main: one warp per (batch, graph) ----------
__global__ void __launch_bounds__(128) gat_main(
    const float* __restrict__ fp,
    const float* __restrict__ uW1, const float* __restrict__ dW1,
    const float* __restrict__ fc2b,
    float* __restrict__ out)
{
    __shared__ __align__(16) float feat[4][1280];   // 20 KB
    __shared__ float Wvs[4][HID];
    __shared__ float part[88];

    const int tid  = threadIdx.x;
    const int w    = tid >> 5;
    const int lane = tid & 31;
    const int unit = blockIdx.x * 4 + w;
    const int b    = unit >> 1;
    const int g    = unit & 1;

    // 1) issue feature loads (10 x LDG.128, coalesced)
    const float4* src = (const float4*)(fp + (long long)b * 2560 + g * 1280);
    float4 v[10];
    #pragma unroll
    for (int i = 0; i < 10; i++) v[i] = src[i * 32 + lane];

    // 2) overlap: precomputed coefficients + this lane's two W1 columns (L1-hot)
    const float* W1 = g ? dW1 : uW1;
    float Cc[7], Ct[7], w1a[7], w1b[7];
    #pragma unroll
    for (int f = 0; f < 7; f++) {
        Cc[f]  = __ldg(&g_C[g][0][f]);
        Ct[f]  = __ldg(&g_C[g][1][f]);
        w1a[f] = __ldg(&W1[f * HID + lane]);
        w1b[f] = __ldg(&W1[f * HID + lane + 32]);
    }

    // 3) stage features into this warp's smem slab
    {
        float4* dst = (float4*)feat[w];
        #pragma unroll
        for (int i = 0; i < 10; i++) dst[i * 32 + lane] = v[i];
    }
    __syncwarp();

    // 4) read owned nodes {lane, lane+32, lane+64, lane+96}
    float x[4][7];
    #pragma unroll
    for (int n = 0; n < 4; n++) {
        const float* r = &feat[w][(n * 32 + lane) * 10];
        float2 p0 = *(const float2*)(r);
        float2 p1 = *(const float2*)(r + 2);
        float2 p2 = *(const float2*)(r + 4);
        x[n][0] = p0.x; x[n][1] = p0.y;
        x[n][2] = p1.x; x[n][3] = p1.y;
        x[n][4] = p2.x; x[n][5] = p2.y;
        x[n][6] = r[6];
    }

    // 5) logits e_j = lrelu(s0 + x_j.Ct); s0 = x_0.Cc broadcast from lane 0
    float s0l = 0.0f;
    #pragma unroll
    for (int f = 0; f < 7; f++) s0l = fmaf(x[0][f], Cc[f], s0l);
    const float s0 = __shfl_sync(0xffffffffu, s0l, 0);

    float e[4];
    #pragma unroll
    for (int n = 0; n < 4; n++) {
        float t = 0.0f;
        #pragma unroll
        for (int f = 0; f < 7; f++) t = fmaf(x[n][f], Ct[f], t);
        float vv = s0 + t;
        e[n] = vv > 0.0f ? vv : 0.2f * vv;
    }
    if (lane == 0) e[0] = -1e30f;          // mask center

    // 6) softmax over 128 logits
    float m = fmaxf(fmaxf(e[0], e[1]), fmaxf(e[2], e[3]));
    #pragma unroll
    for (int o = 16; o; o >>= 1) m = fmaxf(m, __shfl_xor_sync(0xffffffffu, m, o));
    float p[4], z = 0.0f;
    #pragma unroll
    for (int n = 0; n < 4; n++) { p[n] = __expf(e[n] - m); z += p[n]; }

    // 7) reduce z and Y[f] = sum_j p_j x_j[f]  (f is lane-invariant -> valid)
    float Y[7];
    #pragma unroll
    for (int f = 0; f < 7; f++)
        Y[f] = p[0] * x[0][f] + p[1] * x[1][f] + p[2] * x[2][f] + p[3] * x[3][f];
    #pragma unroll
    for (int o = 16; o; o >>= 1) {
        z += __shfl_xor_sync(0xffffffffu, z, o);
        #pragma unroll
        for (int f = 0; f < 7; f++)
            Y[f] += __shfl_xor_sync(0xffffffffu, Y[f], o);
    }
    const float zi = 1.0f / z;
    float x0[7];
    #pragma unroll
    for (int f = 0; f < 7; f++) x0[f] = __shfl_sync(0xffffffffu, x[0][f], 0);

    // 8) Wv[k] = elu(x0.W1[:,k]) + 127*elu((Y/z).W1[:,k])  for k = lane, lane+32
    {
        float ca = 0.0f, la = 0.0f, cb = 0.0f, lb = 0.0f;
        #pragma unroll
        for (int f = 0; f < 7; f++) {
            float yf = Y[f] * zi;
            ca = fmaf(yf,    w1a[f], ca);
            la = fmaf(x0[f], w1a[f], la);
            cb = fmaf(yf,    w1b[f], cb);
            lb = fmaf(x0[f], w1b[f], lb);
        }
        Wvs[w][lane]      = eluf(la) + 127.0f * eluf(ca);
        Wvs[w][lane + 32] = eluf(lb) + 127.0f * eluf(cb);
    }
    __syncthreads();

    // 9) head: out[t] = clip(relu(Wv_u.Mu[t] + Wv_d.Md[t] + b[t]), 0, 10)
    if (tid < 88) {
        const int bb = tid / 44, r = tid % 44, t = r >> 1, half = r & 1;
        const int k0 = half * 32;
        const float* Mu = g_M[0][t];
        const float* Md = g_M[1][t];
        const float* wu = Wvs[2 * bb];
        const float* wd = Wvs[2 * bb + 1];
        float acc = 0.0f;
        #pragma unroll 8
        for (int k = k0; k < k0 + 32; k++)
            acc += wu[k] * __ldg(&Mu[k]) + wd[k] * __ldg(&Md[k]);
        part[tid] = acc;
    }
    __syncthreads();
    if (tid < 44) {
        const int bb = tid / 22, t = tid - bb * 22;
        float acc = part[bb * 44 + t * 2] + part[bb * 44 + t * 2 + 1] + __ldg(&fc2b[t]);
        acc = fminf(fmaxf(acc, 0.0f), 10.0f);
        out[((long long)blockIdx.x * 2 + bb) * TAU + t] = acc;
    }
}

extern "C" void kernel_launch(void* const* d_in, const int* in_sizes, int n_in,
                              void* d_out, int out_size)
{
    const float* fp    = (const float*)d_in[0];
    const float* uW1   = (const float*)d_in[1];
    const float* uA    = (const float*)d_in[2];
    const float* uW2   = (const float*)d_in[3];
    // d_in[4] = u_out_a : provably unused (singleton/uniform layer-2 softmax)
    const float* dW1   = (const float*)d_in[5];
    const float* dA    = (const float*)d_in[6];
    const float* dW2   = (const float*)d_in[7];
    // d_in[8] = d_out_a : unused
    const float* fc2W  = (const float*)d_in[9];
    const float* fc2b  = (const float*)d_in[10];
    float* out = (float*)d_out;

    k_setup<<<23, 128>>>(uW1, uA, uW2, dW1, dA, dW2, fc2W);
    gat_main<<<NB / 2, 128>>>(fp, uW1, dW1, fc2b, out);
}

// round 10
// speedup vs baseline: 2.6141x; 2.6141x over previous
#include <cuda_runtime.h>
#include <math.h>

#define NB    2048
#define HID   64
#define TAU   22

__device__ float g_C[2][2][7];           // [graph][{C1,C2}][f]
__device__ float g_Mt[2][HID][TAU];      // [graph][k][t] = sum_m W2_g[k][m]*fc2W[m][t]

__device__ __forceinline__ float eluf(float x) { return x > 0.0f ? x : (__expf(x) - 1.0f); }

// ---------- setup: batch-invariant precompute (~1us) ----------
__global__ void __launch_bounds__(128) k_setup(
    const float* __restrict__ uW1, const float* __restrict__ uA,
    const float* __restrict__ uW2,
    const float* __restrict__ dW1, const float* __restrict__ dA,
    const float* __restrict__ dW2,
    const float* __restrict__ fc2W)
{
    const int id = blockIdx.x * 128 + threadIdx.x;   // 23*128 = 2944 >= 2844
    if (id < 28) {
        int g = id / 14, rem = id % 14, which = rem / 7, f = rem % 7;
        const float* W1 = g ? dW1 : uW1;
        const float* A  = (g ? dA : uA) + which * HID;
        float acc = 0.0f;
        #pragma unroll 8
        for (int k = 0; k < HID; k++) acc = fmaf(W1[f * HID + k], A[k], acc);
        g_C[g][which][f] = acc;
    } else if (id - 28 < 2 * HID * TAU) {
        int e = id - 28;
        int g = e / (HID * TAU); e -= g * HID * TAU;
        int k = e / TAU, t = e - k * TAU;
        const float* W2 = g ? dW2 : uW2;
        float acc = 0.0f;
        #pragma unroll 8
        for (int m = 0; m < HID; m++)
            acc = fmaf(W2[k * HID + m], fc2W[m * TAU + t], acc);
        g_Mt[g][k][t] = acc;
    }
}

// ---------- main: one warp per (batch, graph) ----------
__global__ void __launch_bounds__(128) gat_main(
    const float* __restrict__ fp,
    const float* __restrict__ uW1, const float* __restrict__ dW1,
    const float* __restrict__ fc2b,
    float* __restrict__ out)
{
    __shared__ __align__(16) float feat[4][1280];   // 20 KB
    __shared__ float Wvs[4][HID];
    __shared__ float part[4][TAU];

    const int tid  = threadIdx.x;
    const int w    = tid >> 5;
    const int lane = tid & 31;
    const int unit = blockIdx.x * 4 + w;
    const int b    = unit >> 1;
    const int g    = unit & 1;

    // 1) issue feature loads (10 x LDG.128, coalesced)
    const float4* src = (const float4*)(fp + (long long)b * 2560 + g * 1280);
    float4 v[10];
    #pragma unroll
    for (int i = 0; i < 10; i++) v[i] = src[i * 32 + lane];

    // 2) overlap: precomputed coefficients + this lane's two W1 columns (L1-hot)
    const float* W1 = g ? dW1 : uW1;
    float Cc[7], Ct[7], w1a[7], w1b[7];
    #pragma unroll
    for (int f = 0; f < 7; f++) {
        Cc[f]  = __ldg(&g_C[g][0][f]);
        Ct[f]  = __ldg(&g_C[g][1][f]);
        w1a[f] = __ldg(&W1[f * HID + lane]);
        w1b[f] = __ldg(&W1[f * HID + lane + 32]);
    }

    // 3) stage features into this warp's smem slab
    {
        float4* dst = (float4*)feat[w];
        #pragma unroll
        for (int i = 0; i < 10; i++) dst[i * 32 + lane] = v[i];
    }
    __syncwarp();

    // 4) read owned nodes {lane, lane+32, lane+64, lane+96}
    float x[4][7];
    #pragma unroll
    for (int n = 0; n < 4; n++) {
        const float* r = &feat[w][(n * 32 + lane) * 10];
        float2 p0 = *(const float2*)(r);
        float2 p1 = *(const float2*)(r + 2);
        float2 p2 = *(const float2*)(r + 4);
        x[n][0] = p0.x; x[n][1] = p0.y;
        x[n][2] = p1.x; x[n][3] = p1.y;
        x[n][4] = p2.x; x[n][5] = p2.y;
        x[n][6] = r[6];
    }

    // 5) logits e_j = lrelu(s0 + x_j.Ct); s0 = x_0.Cc broadcast from lane 0
    float s0l = 0.0f;
    #pragma unroll
    for (int f = 0; f < 7; f++) s0l = fmaf(x[0][f], Cc[f], s0l);
    const float s0 = __shfl_sync(0xffffffffu, s0l, 0);

    float e[4];
    #pragma unroll
    for (int n = 0; n < 4; n++) {
        float t = 0.0f;
        #pragma unroll
        for (int f = 0; f < 7; f++) t = fmaf(x[n][f], Ct[f], t);
        float vv = s0 + t;
        e[n] = vv > 0.0f ? vv : 0.2f * vv;
    }
    if (lane == 0) e[0] = -1e30f;          // mask center

    // 6) softmax over 128 logits
    float m = fmaxf(fmaxf(e[0], e[1]), fmaxf(e[2], e[3]));
    #pragma unroll
    for (int o = 16; o; o >>= 1) m = fmaxf(m, __shfl_xor_sync(0xffffffffu, m, o));
    float p[4], z = 0.0f;
    #pragma unroll
    for (int n = 0; n < 4; n++) { p[n] = __expf(e[n] - m); z += p[n]; }

    // 7) reduce z and Y[f] = sum_j p_j x_j[f]
    float Y[7];
    #pragma unroll
    for (int f = 0; f < 7; f++)
        Y[f] = p[0] * x[0][f] + p[1] * x[1][f] + p[2] * x[2][f] + p[3] * x[3][f];
    #pragma unroll
    for (int o = 16; o; o >>= 1) {
        z += __shfl_xor_sync(0xffffffffu, z, o);
        #pragma unroll
        for (int f = 0; f < 7; f++)
            Y[f] += __shfl_xor_sync(0xffffffffu, Y[f], o);
    }
    const float zi = 1.0f / z;
    float x0[7];
    #pragma unroll
    for (int f = 0; f < 7; f++) x0[f] = __shfl_sync(0xffffffffu, x[0][f], 0);

    // 8) Wv[k] = elu(x0.W1[:,k]) + 127*elu((Y/z).W1[:,k])  for k = lane, lane+32
    {
        float ca = 0.0f, la = 0.0f, cb = 0.0f, lb = 0.0f;
        #pragma unroll
        for (int f = 0; f < 7; f++) {
            float yf = Y[f] * zi;
            ca = fmaf(yf,    w1a[f], ca);
            la = fmaf(x0[f], w1a[f], la);
            cb = fmaf(yf,    w1b[f], cb);
            lb = fmaf(x0[f], w1b[f], lb);
        }
        Wvs[w][lane]      = eluf(la) + 127.0f * eluf(ca);
        Wvs[w][lane + 32] = eluf(lb) + 127.0f * eluf(cb);
    }
    __syncwarp();

    // 9) per-warp head partial: part[w][t] = sum_k Wv[k] * Mt[g][k][t]
    //    lane = t (22 active). LDG coalesced (22 consecutive floats, L1-hot);
    //    Wvs[w][k] is a uniform-address LDS broadcast. No shuffle reduction.
    if (lane < TAU) {
        float acc = 0.0f;
        #pragma unroll 8
        for (int k = 0; k < HID; k++)
            acc = fmaf(Wvs[w][k], __ldg(&g_Mt[g][k][lane]), acc);
        part[w][lane] = acc;
    }
    __syncthreads();

    // 10) combine u+d, bias, relu-clip, store (44 threads)
    if (tid < 2 * TAU) {
        const int bb = tid / TAU, t = tid - bb * TAU;
        float acc = part[2 * bb][t] + part[2 * bb + 1][t] + __ldg(&fc2b[t]);
        acc = fminf(fmaxf(acc, 0.0f), 10.0f);
        out[((long long)blockIdx.x * 2 + bb) * TAU + t] = acc;
    }
}

extern "C" void kernel_launch(void* const* d_in, const int* in_sizes, int n_in,
                              void* d_out, int out_size)
{
    const float* fp    = (const float*)d_in[0];
    const float* uW1   = (const float*)d_in[1];
    const float* uA    = (const float*)d_in[2];
    const float* uW2   = (const float*)d_in[3];
    // d_in[4] = u_out_a : provably unused (singleton/uniform layer-2 softmax)
    const float* dW1   = (const float*)d_in[5];
    const float* dA    = (const float*)d_in[6];
    const float* dW2   = (const float*)d_in[7];
    // d_in[8] = d_out_a : unused
    const float* fc2W  = (const float*)d_in[9];
    const float* fc2b  = (const float*)d_in[10];
    float* out = (float*)d_out;

    k_setup<<<23, 128>>>(uW1, uA, uW2, dW1, dA, dW2, fc2W);
    gat_main<<<NB / 2, 128>>>(fp, uW1, dW1, fc2b, out);
}

// round 13
// speedup vs baseline: 2.7004x; 1.0330x over previous
#include <cuda_runtime.h>
#include <math.h>

#define NB    2048
#define HID   64
#define TAU   22

__device__ float g_C[2][2][7];           // [graph][{C1,C2}][f]
__device__ float g_Mt[2][HID][TAU];      // [graph][k][t] = sum_m W2_g[k][m]*fc2W[m][t]

__device__ __forceinline__ float eluf(float x) { return x > 0.0f ? x : (__expf(x) - 1.0f); }

// ---------- setup: batch-invariant precompute ----------
// 28 C-dots (1 thread each) + 2816 Mt-dots (2 threads each, 32 m-iters, shfl combine)
__global__ void __launch_bounds__(128) k_setup(
    const float* __restrict__ uW1, const float* __restrict__ uA,
    const float* __restrict__ uW2,
    const float* __restrict__ dW1, const float* __restrict__ dA,
    const float* __restrict__ dW2,
    const float* __restrict__ fc2W)
{
    const int id = blockIdx.x * 128 + threadIdx.x;   // 45*128 = 5760 >= 28+5632
    if (id < 28) {
        int g = id / 14, rem = id % 14, which = rem / 7, f = rem % 7;
        const float* W1 = g ? dW1 : uW1;
        const float* A  = (g ? dA : uA) + which * HID;
        float acc = 0.0f;
        #pragma unroll 8
        for (int k = 0; k < HID; k++) acc = fmaf(W1[f * HID + k], A[k], acc);
        g_C[g][which][f] = acc;
    }
    const int id2 = id - 28;
    if (id2 >= 0 && id2 < 2 * HID * TAU * 2) {
        int entry = id2 >> 1, half = id2 & 1;
        int g = entry / (HID * TAU); entry -= g * HID * TAU;
        int k = entry / TAU, t = entry - k * TAU;
        const float* W2 = (g ? dW2 : uW2) + k * HID + half * 32;
        const float* F  = fc2W + half * 32 * TAU + t;
        float acc = 0.0f;
        #pragma unroll
        for (int i = 0; i < 8; i++) {
            float4 w4 = *(const float4*)(W2 + i * 4);
            acc = fmaf(w4.x, __ldg(F + (i * 4 + 0) * TAU), acc);
            acc = fmaf(w4.y, __ldg(F + (i * 4 + 1) * TAU), acc);
            acc = fmaf(w4.z, __ldg(F + (i * 4 + 2) * TAU), acc);
            acc = fmaf(w4.w, __ldg(F + (i * 4 + 3) * TAU), acc);
        }
        acc += __shfl_down_sync(0xffffffffu, acc, 1);
        if (half == 0) g_Mt[g][k][t] = acc;
    }
}

// ---------- main: one warp per (batch, graph) ----------
__global__ void __launch_bounds__(128) gat_main(
    const float* __restrict__ fp,
    const float* __restrict__ uW1, const float* __restrict__ dW1,
    const float* __restrict__ fc2b,
    float* __restrict__ out)
{
    __shared__ __align__(16) float feat[4][1280];   // 20 KB
    __shared__ float Wvs[4][HID];
    __shared__ float part[4][TAU];

    const int tid  = threadIdx.x;
    const int w    = tid >> 5;
    const int lane = tid & 31;
    const int unit = blockIdx.x * 4 + w;
    const int b    = unit >> 1;
    const int g    = unit & 1;

    // 1) issue feature loads (10 x LDG.128, coalesced)
    const float4* src = (const float4*)(fp + (long long)b * 2560 + g * 1280);
    float4 v[10];
    #pragma unroll
    for (int i = 0; i < 10; i++) v[i] = src[i * 32 + lane];

    // 2) overlap: precomputed coefficients + this lane's two W1 columns (L1-hot)
    const float* W1 = g ? dW1 : uW1;
    float Cc[7], Ct[7], w1a[7], w1b[7];
    #pragma unroll
    for (int f = 0; f < 7; f++) {
        Cc[f]  = __ldg(&g_C[g][0][f]);
        Ct[f]  = __ldg(&g_C[g][1][f]);
        w1a[f] = __ldg(&W1[f * HID + lane]);
        w1b[f] = __ldg(&W1[f * HID + lane + 32]);
    }

    // 3) stage features into this warp's smem slab
    {
        float4* dst = (float4*)feat[w];
        #pragma unroll
        for (int i = 0; i < 10; i++) dst[i * 32 + lane] = v[i];
    }
    __syncwarp();

    // 4) center features via uniform-address LDS broadcast (no shuffles);
    //    every lane computes s0 locally
    float x0[7];
    {
        float2 q0 = *(const float2*)&feat[w][0];
        float2 q1 = *(const float2*)&feat[w][2];
        float2 q2 = *(const float2*)&feat[w][4];
        x0[0] = q0.x; x0[1] = q0.y; x0[2] = q1.x; x0[3] = q1.y;
        x0[4] = q2.x; x0[5] = q2.y; x0[6] = feat[w][6];
    }
    float s0 = 0.0f;
    #pragma unroll
    for (int f = 0; f < 7; f++) s0 = fmaf(x0[f], Cc[f], s0);

    // 5) read owned nodes {lane, lane+32, lane+64, lane+96}
    float x[4][7];
    #pragma unroll
    for (int n = 0; n < 4; n++) {
        const float* r = &feat[w][(n * 32 + lane) * 10];
        float2 p0 = *(const float2*)(r);
        float2 p1 = *(const float2*)(r + 2);
        float2 p2 = *(const float2*)(r + 4);
        x[n][0] = p0.x; x[n][1] = p0.y;
        x[n][2] = p1.x; x[n][3] = p1.y;
        x[n][4] = p2.x; x[n][5] = p2.y;
        x[n][6] = r[6];
    }

    // 6) logits + exp (shift-free: |logits| ~ O(1), overflow impossible;
    //    softmax is shift-invariant so result matches reference)
    float p[4], z = 0.0f;
    #pragma unroll
    for (int n = 0; n < 4; n++) {
        float t = 0.0f;
        #pragma unroll
        for (int f = 0; f < 7; f++) t = fmaf(x[n][f], Ct[f], t);
        float vv = s0 + t;
        vv = vv > 0.0f ? vv : 0.2f * vv;
        if (n == 0 && lane == 0) vv = -1e30f;   // mask center -> exp = 0
        p[n] = __expf(vv);
        z += p[n];
    }

    // 7) reduce z and Y[f] = sum_j p_j x_j[f]  (8 parallel xor-reductions)
    float Y[7];
    #pragma unroll
    for (int f = 0; f < 7; f++)
        Y[f] = p[0] * x[0][f] + p[1] * x[1][f] + p[2] * x[2][f] + p[3] * x[3][f];
    #pragma unroll
    for (int o = 16; o; o >>= 1) {
        z += __shfl_xor_sync(0xffffffffu, z, o);
        #pragma unroll
        for (int f = 0; f < 7; f++)
            Y[f] += __shfl_xor_sync(0xffffffffu, Y[f], o);
    }
    const float zi = 1.0f / z;

    // 8) Wv[k] = elu(x0.W1[:,k]) + 127*elu((Y/z).W1[:,k])  for k = lane, lane+32
    {
        float ca = 0.0f, la = 0.0f, cb = 0.0f, lb = 0.0f;
        #pragma unroll
        for (int f = 0; f < 7; f++) {
            float yf = Y[f] * zi;
            ca = fmaf(yf,    w1a[f], ca);
            la = fmaf(x0[f], w1a[f], la);
            cb = fmaf(yf,    w1b[f], cb);
            lb = fmaf(x0[f], w1b[f], lb);
        }
        Wvs[w][lane]      = eluf(la) + 127.0f * eluf(ca);
        Wvs[w][lane + 32] = eluf(lb) + 127.0f * eluf(cb);
    }
    __syncwarp();

    // 9) per-warp head partial: part[w][t] = sum_k Wv[k] * Mt[g][k][t]
    //    (coalesced L1-hot LDG; Wvs uniform-address LDS broadcast)
    if (lane < TAU) {
        float acc = 0.0f;
        #pragma unroll 8
        for (int k = 0; k < HID; k++)
            acc = fmaf(Wvs[w][k], __ldg(&g_Mt[g][k][lane]), acc);
        part[w][lane] = acc;
    }
    __syncthreads();

    // 10) combine u+d, bias, relu-clip, store (44 threads)
    if (tid < 2 * TAU) {
        const int bb = (tid >= TAU);
        const int t  = tid - bb * TAU;
        float acc = part[2 * bb][t] + part[2 * bb + 1][t] + __ldg(&fc2b[t]);
        acc = fminf(fmaxf(acc, 0.0f), 10.0f);
        out[((long long)(blockIdx.x * 2 + bb)) * TAU + t] = acc;
    }
}

extern "C" void kernel_launch(void* const* d_in, const int* in_sizes, int n_in,
                              void* d_out, int out_size)
{
    const float* fp    = (const float*)d_in[0];
    const float* uW1   = (const float*)d_in[1];
    const float* uA    = (const float*)d_in[2];
    const float* uW2   = (const float*)d_in[3];
    // d_in[4] = u_out_a : provably unused (singleton/uniform layer-2 softmax)
    const float* dW1   = (const float*)d_in[5];
    const float* dA    = (const float*)d_in[6];
    const float* dW2   = (const float*)d_in[7];
    // d_in[8] = d_out_a : unused
    const float* fc2W  = (const float*)d_in[9];
    const float* fc2b  = (const float*)d_in[10];
    float* out = (float*)d_out;

    k_setup<<<45, 128>>>(uW1, uA, uW2, dW1, dA, dW2, fc2W);
    gat_main<<<NB / 2, 128>>>(fp, uW1, dW1, fc2b, out);
}